// round 3
// baseline (speedup 1.0000x reference)
#include <cuda_runtime.h>
#include <cuda_bf16.h>

// GCN: h1 = relu(GCNConv(x, W1, b1)); h2 = relu(GCNConv(h1, W2, b2));
// out = mean_pool_per_graph(h2) @ Wlin + blin
//
// Factorization: GCNConv(x)_i = dinv[i] * ( sum_{e:dst=i} hs[src_e] + hs[i] ) + b
// where hs = (x @ W) * dinv[row],  dinv = rsqrt(deg+1).
//
// NOTE: all scratch is __device__ globals referenced ONLY from device code
// (a __device__ symbol passed as a host-side kernel arg is NOT a valid
// device pointer — that was the round-1 crash).

#define NN 50000
#define NE 800000
#define HID 64

// ---- scratch (static device globals; no allocation allowed) ----
__device__ __align__(16) float g_deg[NN];
__device__ __align__(16) float g_dinv[NN];
__device__ __align__(16) float g_hs[NN * HID];   // hs for current layer
__device__ __align__(16) float g_agg[NN * HID];  // scatter accumulator
__device__ __align__(16) float g_out1[NN * HID]; // layer-1 activation
__device__ __align__(16) float g_gbuf[128];      // [0:64) graph sums, [64:128) counts

// ---------------------------------------------------------------------------
// 1) deg init
__global__ void k_deg_init(int n) {
    int i = blockIdx.x * blockDim.x + threadIdx.x;
    if (i < n) g_deg[i] = 1.0f;
}

// 2) deg count: deg[dst] += 1 per edge
__global__ void k_deg_count(const int* __restrict__ dst, int ne) {
    int e = blockIdx.x * blockDim.x + threadIdx.x;
    if (e < ne) atomicAdd(&g_deg[dst[e]], 1.0f);
}

// 3) dinv = rsqrt(deg); zero agg
__global__ void k_dinv_zero(int n) {
    int i = blockIdx.x * blockDim.x + threadIdx.x;
    if (i < n) g_dinv[i] = rsqrtf(g_deg[i]);
    if (i < n * (HID / 4)) {
        reinterpret_cast<float4*>(g_agg)[i] = make_float4(0.f, 0.f, 0.f, 0.f);
    }
}

// zero agg (+ graph buffers) for layer 2
__global__ void k_zero2(int n) {
    int i = blockIdx.x * blockDim.x + threadIdx.x;
    if (i < 128) g_gbuf[i] = 0.0f;
    if (i < n * (HID / 4)) {
        reinterpret_cast<float4*>(g_agg)[i] = make_float4(0.f, 0.f, 0.f, 0.f);
    }
}

// ---------------------------------------------------------------------------
// GEMM: g_hs[r, 0:64] = (X[r, 0:K] @ W[K, 64]) * dinv[r]
// X == nullptr -> read g_out1 (layer 2). Output always g_hs (device symbol).
// Block: 256 threads, 64-row tile, K processed in 64-chunks.
template <int K>
__global__ __launch_bounds__(256) void k_gemm(
    const float* __restrict__ Xin, const float* __restrict__ W, int nrows)
{
    const float* __restrict__ X = Xin ? Xin : g_out1;

    __shared__ float Xs[64][68];   // padded stride: conflict-free column reads
    __shared__ float Ws[64][64];

    const int tid = threadIdx.x;
    const int row0 = blockIdx.x * 64;
    const int tx = tid & 15;   // col group: cols tx*4 .. tx*4+3
    const int ty = tid >> 4;   // row group: rows ty*4 .. ty*4+3

    float acc[4][4] = {};

    for (int k0 = 0; k0 < K; k0 += 64) {
        // load W chunk [64 x 64] via float4
        for (int i = tid; i < 64 * 16; i += 256) {
            reinterpret_cast<float4*>(&Ws[0][0])[i] =
                reinterpret_cast<const float4*>(W + (size_t)k0 * 64)[i];
        }
        // load X chunk [64 rows x 64 cols]
        for (int i = tid; i < 64 * 16; i += 256) {
            int r = i >> 4;
            int c = (i & 15) * 4;
            int gr = row0 + r;
            float4 v = make_float4(0.f, 0.f, 0.f, 0.f);
            if (gr < nrows)
                v = *reinterpret_cast<const float4*>(X + (size_t)gr * K + k0 + c);
            Xs[r][c + 0] = v.x; Xs[r][c + 1] = v.y;
            Xs[r][c + 2] = v.z; Xs[r][c + 3] = v.w;
        }
        __syncthreads();

        #pragma unroll 8
        for (int kk = 0; kk < 64; kk++) {
            float4 wv = *reinterpret_cast<const float4*>(&Ws[kk][tx * 4]);
            float x0 = Xs[ty * 4 + 0][kk];
            float x1 = Xs[ty * 4 + 1][kk];
            float x2 = Xs[ty * 4 + 2][kk];
            float x3 = Xs[ty * 4 + 3][kk];
            acc[0][0] += x0 * wv.x; acc[0][1] += x0 * wv.y;
            acc[0][2] += x0 * wv.z; acc[0][3] += x0 * wv.w;
            acc[1][0] += x1 * wv.x; acc[1][1] += x1 * wv.y;
            acc[1][2] += x1 * wv.z; acc[1][3] += x1 * wv.w;
            acc[2][0] += x2 * wv.x; acc[2][1] += x2 * wv.y;
            acc[2][2] += x2 * wv.z; acc[2][3] += x2 * wv.w;
            acc[3][0] += x3 * wv.x; acc[3][1] += x3 * wv.y;
            acc[3][2] += x3 * wv.z; acc[3][3] += x3 * wv.w;
        }
        __syncthreads();
    }

    #pragma unroll
    for (int r = 0; r < 4; r++) {
        int gr = row0 + ty * 4 + r;
        if (gr < nrows) {
            float s = g_dinv[gr];
            float4 o = make_float4(acc[r][0] * s, acc[r][1] * s,
                                   acc[r][2] * s, acc[r][3] * s);
            reinterpret_cast<float4*>(g_hs + (size_t)gr * 64)[tx] = o;
        }
    }
}

// ---------------------------------------------------------------------------
// Edge scatter: agg[dst] += hs[src]   (64 floats = 16 lanes x float4 per edge)
__global__ __launch_bounds__(256) void k_scatter(
    const int* __restrict__ src, const int* __restrict__ dst, int ne)
{
    int idx = blockIdx.x * blockDim.x + threadIdx.x;
    int e = idx >> 4;
    if (e >= ne) return;
    int q = idx & 15;
    int s = __ldg(src + e);
    int d = __ldg(dst + e);
    float4 v = reinterpret_cast<const float4*>(g_hs)[(size_t)s * 16 + q];
    float* p = g_agg + ((size_t)d * 64 + q * 4);
    asm volatile("red.global.add.v4.f32 [%0], {%1,%2,%3,%4};"
                 :: "l"(p), "f"(v.x), "f"(v.y), "f"(v.z), "f"(v.w)
                 : "memory");
}

// ---------------------------------------------------------------------------
// Post layer 1: out1 = relu(dinv[i]*(agg[i]+hs[i]) + b1)
__global__ void k_post1(const float* __restrict__ b, int n) {
    int idx = blockIdx.x * blockDim.x + threadIdx.x;  // over n*16 float4s
    if (idx >= n * 16) return;
    int row = idx >> 4;
    int q = idx & 15;
    float s = g_dinv[row];
    float4 a = reinterpret_cast<const float4*>(g_agg)[idx];
    float4 h = reinterpret_cast<const float4*>(g_hs)[idx];
    float4 bb = reinterpret_cast<const float4*>(b)[q];
    float4 o;
    o.x = fmaxf(0.f, s * (a.x + h.x) + bb.x);
    o.y = fmaxf(0.f, s * (a.y + h.y) + bb.y);
    o.z = fmaxf(0.f, s * (a.z + h.z) + bb.z);
    o.w = fmaxf(0.f, s * (a.w + h.w) + bb.w);
    reinterpret_cast<float4*>(g_out1)[idx] = o;
}

// ---------------------------------------------------------------------------
// Post layer 2 fused with pooling head:
// per node: v = relu(dinv*(agg+hs)+b2);  dot(v, Wlin) -> atomicAdd to graph sum
__global__ __launch_bounds__(256) void k_post2_reduce(
    const float* __restrict__ b2, const float* __restrict__ Wlin,
    const int* __restrict__ batch, int n)
{
    int node = (blockIdx.x * blockDim.x + threadIdx.x) >> 5;
    int lane = threadIdx.x & 31;
    if (node >= n) return;
    float s = g_dinv[node];
    float acc = 0.f;
    #pragma unroll
    for (int j0 = 0; j0 < 64; j0 += 32) {
        int j = j0 + lane;
        float v = fmaxf(0.f,
            s * (g_agg[(size_t)node * 64 + j] + g_hs[(size_t)node * 64 + j])
            + __ldg(b2 + j));
        acc += v * __ldg(Wlin + j);
    }
    #pragma unroll
    for (int o = 16; o; o >>= 1) acc += __shfl_xor_sync(0xFFFFFFFFu, acc, o);
    if (lane == 0) {
        int g = __ldg(batch + node);
        atomicAdd(&g_gbuf[g], acc);
        atomicAdd(&g_gbuf[64 + g], 1.0f);
    }
}

// ---------------------------------------------------------------------------
__global__ void k_finalize(const float* __restrict__ blin, float* __restrict__ out) {
    int g = threadIdx.x;
    if (g < 64) out[g] = g_gbuf[g] / fmaxf(g_gbuf[64 + g], 1.0f) + blin[0];
}

// ---------------------------------------------------------------------------
extern "C" void kernel_launch(void* const* d_in, const int* in_sizes, int n_in,
                              void* d_out, int out_size)
{
    const float* x     = (const float*)d_in[0];
    const int*   eidx  = (const int*)d_in[1];
    const int*   batch = (const int*)d_in[2];
    const float* W1    = (const float*)d_in[3];
    const float* b1    = (const float*)d_in[4];
    const float* W2    = (const float*)d_in[5];
    const float* b2    = (const float*)d_in[6];
    const float* Wlin  = (const float*)d_in[7];
    const float* blin  = (const float*)d_in[8];
    float* out = (float*)d_out;

    const int N = in_sizes[0] / 128;   // 50000
    const int E = in_sizes[1] / 2;     // 800000
    const int* src = eidx;
    const int* dst = eidx + E;

    const int T = 256;

    // degree + norm
    k_deg_init<<<(N + T - 1) / T, T>>>(N);
    k_deg_count<<<(E + T - 1) / T, T>>>(dst, E);
    k_dinv_zero<<<(N * 16 + T - 1) / T, T>>>(N);

    // layer 1
    k_gemm<128><<<(N + 63) / 64, 256>>>(x, W1, N);
    {
        long long w = (long long)E * 16;
        k_scatter<<<(int)((w + T - 1) / T), T>>>(src, dst, E);
    }
    k_post1<<<(N * 16 + T - 1) / T, T>>>(b1, N);

    // layer 2
    k_zero2<<<(N * 16 + T - 1) / T, T>>>(N);
    k_gemm<64><<<(N + 63) / 64, 256>>>(nullptr, W2, N);
    {
        long long w = (long long)E * 16;
        k_scatter<<<(int)((w + T - 1) / T), T>>>(src, dst, E);
    }

    // fused post + pooling head
    k_post2_reduce<<<(N * 32 + T - 1) / T, T>>>(b2, Wlin, batch, N);
    k_finalize<<<1, 64>>>(blin, out);
}

// round 4
// speedup vs baseline: 1.0078x; 1.0078x over previous
#include <cuda_runtime.h>
#include <cuda_bf16.h>

// GCN: h1 = relu(GCNConv(x, W1, b1)); h2 = relu(GCNConv(h1, W2, b2));
// out = mean_pool_per_graph(h2) @ Wlin + blin
//
// Factorization: GCNConv(x)_i = dinv[i] * ( sum_{e:dst=i} hs[src_e] + hs[i] ) + b
// where hs = (x @ W) * dinv[row],  dinv = rsqrt(deg+1).
//
// NOTE: all scratch is __device__ globals referenced ONLY from device code
// (a __device__ symbol passed as a host-side kernel arg is NOT a valid
// device pointer — that was the round-1 crash).

#define NN 50000
#define NE 800000
#define HID 64

// ---- scratch (static device globals; no allocation allowed) ----
__device__ __align__(16) float g_deg[NN];
__device__ __align__(16) float g_dinv[NN];
__device__ __align__(16) float g_hs[NN * HID];   // hs for current layer
__device__ __align__(16) float g_agg[NN * HID];  // scatter accumulator
__device__ __align__(16) float g_out1[NN * HID]; // layer-1 activation
__device__ __align__(16) float g_gbuf[128];      // [0:64) graph sums, [64:128) counts

// ---------------------------------------------------------------------------
// 1) deg init
__global__ void k_deg_init(int n) {
    int i = blockIdx.x * blockDim.x + threadIdx.x;
    if (i < n) g_deg[i] = 1.0f;
}

// 2) deg count: deg[dst] += 1 per edge
__global__ void k_deg_count(const int* __restrict__ dst, int ne) {
    int e = blockIdx.x * blockDim.x + threadIdx.x;
    if (e < ne) atomicAdd(&g_deg[dst[e]], 1.0f);
}

// 3) dinv = rsqrt(deg); zero agg
__global__ void k_dinv_zero(int n) {
    int i = blockIdx.x * blockDim.x + threadIdx.x;
    if (i < n) g_dinv[i] = rsqrtf(g_deg[i]);
    if (i < n * (HID / 4)) {
        reinterpret_cast<float4*>(g_agg)[i] = make_float4(0.f, 0.f, 0.f, 0.f);
    }
}

// zero agg (+ graph buffers) for layer 2
__global__ void k_zero2(int n) {
    int i = blockIdx.x * blockDim.x + threadIdx.x;
    if (i < 128) g_gbuf[i] = 0.0f;
    if (i < n * (HID / 4)) {
        reinterpret_cast<float4*>(g_agg)[i] = make_float4(0.f, 0.f, 0.f, 0.f);
    }
}

// ---------------------------------------------------------------------------
// GEMM: g_hs[r, 0:64] = (X[r, 0:K] @ W[K, 64]) * dinv[r]
// X == nullptr -> read g_out1 (layer 2). Output always g_hs (device symbol).
// Block: 256 threads, 64-row tile, K processed in 64-chunks.
template <int K>
__global__ __launch_bounds__(256) void k_gemm(
    const float* __restrict__ Xin, const float* __restrict__ W, int nrows)
{
    const float* __restrict__ X = Xin ? Xin : g_out1;

    __shared__ float Xs[64][68];   // padded stride: conflict-free column reads
    __shared__ float Ws[64][64];

    const int tid = threadIdx.x;
    const int row0 = blockIdx.x * 64;
    const int tx = tid & 15;   // col group: cols tx*4 .. tx*4+3
    const int ty = tid >> 4;   // row group: rows ty*4 .. ty*4+3

    float acc[4][4] = {};

    for (int k0 = 0; k0 < K; k0 += 64) {
        // load W chunk [64 x 64] via float4
        for (int i = tid; i < 64 * 16; i += 256) {
            reinterpret_cast<float4*>(&Ws[0][0])[i] =
                reinterpret_cast<const float4*>(W + (size_t)k0 * 64)[i];
        }
        // load X chunk [64 rows x 64 cols]
        for (int i = tid; i < 64 * 16; i += 256) {
            int r = i >> 4;
            int c = (i & 15) * 4;
            int gr = row0 + r;
            float4 v = make_float4(0.f, 0.f, 0.f, 0.f);
            if (gr < nrows)
                v = *reinterpret_cast<const float4*>(X + (size_t)gr * K + k0 + c);
            Xs[r][c + 0] = v.x; Xs[r][c + 1] = v.y;
            Xs[r][c + 2] = v.z; Xs[r][c + 3] = v.w;
        }
        __syncthreads();

        #pragma unroll 8
        for (int kk = 0; kk < 64; kk++) {
            float4 wv = *reinterpret_cast<const float4*>(&Ws[kk][tx * 4]);
            float x0 = Xs[ty * 4 + 0][kk];
            float x1 = Xs[ty * 4 + 1][kk];
            float x2 = Xs[ty * 4 + 2][kk];
            float x3 = Xs[ty * 4 + 3][kk];
            acc[0][0] += x0 * wv.x; acc[0][1] += x0 * wv.y;
            acc[0][2] += x0 * wv.z; acc[0][3] += x0 * wv.w;
            acc[1][0] += x1 * wv.x; acc[1][1] += x1 * wv.y;
            acc[1][2] += x1 * wv.z; acc[1][3] += x1 * wv.w;
            acc[2][0] += x2 * wv.x; acc[2][1] += x2 * wv.y;
            acc[2][2] += x2 * wv.z; acc[2][3] += x2 * wv.w;
            acc[3][0] += x3 * wv.x; acc[3][1] += x3 * wv.y;
            acc[3][2] += x3 * wv.z; acc[3][3] += x3 * wv.w;
        }
        __syncthreads();
    }

    #pragma unroll
    for (int r = 0; r < 4; r++) {
        int gr = row0 + ty * 4 + r;
        if (gr < nrows) {
            float s = g_dinv[gr];
            float4 o = make_float4(acc[r][0] * s, acc[r][1] * s,
                                   acc[r][2] * s, acc[r][3] * s);
            reinterpret_cast<float4*>(g_hs + (size_t)gr * 64)[tx] = o;
        }
    }
}

// ---------------------------------------------------------------------------
// Edge scatter: agg[dst] += hs[src]   (64 floats = 16 lanes x float4 per edge)
__global__ __launch_bounds__(256) void k_scatter(
    const int* __restrict__ src, const int* __restrict__ dst, int ne)
{
    int idx = blockIdx.x * blockDim.x + threadIdx.x;
    int e = idx >> 4;
    if (e >= ne) return;
    int q = idx & 15;
    int s = __ldg(src + e);
    int d = __ldg(dst + e);
    float4 v = reinterpret_cast<const float4*>(g_hs)[(size_t)s * 16 + q];
    float* p = g_agg + ((size_t)d * 64 + q * 4);
    asm volatile("red.global.add.v4.f32 [%0], {%1,%2,%3,%4};"
                 :: "l"(p), "f"(v.x), "f"(v.y), "f"(v.z), "f"(v.w)
                 : "memory");
}

// ---------------------------------------------------------------------------
// Post layer 1: out1 = relu(dinv[i]*(agg[i]+hs[i]) + b1)
__global__ void k_post1(const float* __restrict__ b, int n) {
    int idx = blockIdx.x * blockDim.x + threadIdx.x;  // over n*16 float4s
    if (idx >= n * 16) return;
    int row = idx >> 4;
    int q = idx & 15;
    float s = g_dinv[row];
    float4 a = reinterpret_cast<const float4*>(g_agg)[idx];
    float4 h = reinterpret_cast<const float4*>(g_hs)[idx];
    float4 bb = reinterpret_cast<const float4*>(b)[q];
    float4 o;
    o.x = fmaxf(0.f, s * (a.x + h.x) + bb.x);
    o.y = fmaxf(0.f, s * (a.y + h.y) + bb.y);
    o.z = fmaxf(0.f, s * (a.z + h.z) + bb.z);
    o.w = fmaxf(0.f, s * (a.w + h.w) + bb.w);
    reinterpret_cast<float4*>(g_out1)[idx] = o;
}

// ---------------------------------------------------------------------------
// Post layer 2 fused with pooling head:
// per node: v = relu(dinv*(agg+hs)+b2);  dot(v, Wlin) -> atomicAdd to graph sum
__global__ __launch_bounds__(256) void k_post2_reduce(
    const float* __restrict__ b2, const float* __restrict__ Wlin,
    const int* __restrict__ batch, int n)
{
    int node = (blockIdx.x * blockDim.x + threadIdx.x) >> 5;
    int lane = threadIdx.x & 31;
    if (node >= n) return;
    float s = g_dinv[node];
    float acc = 0.f;
    #pragma unroll
    for (int j0 = 0; j0 < 64; j0 += 32) {
        int j = j0 + lane;
        float v = fmaxf(0.f,
            s * (g_agg[(size_t)node * 64 + j] + g_hs[(size_t)node * 64 + j])
            + __ldg(b2 + j));
        acc += v * __ldg(Wlin + j);
    }
    #pragma unroll
    for (int o = 16; o; o >>= 1) acc += __shfl_xor_sync(0xFFFFFFFFu, acc, o);
    if (lane == 0) {
        int g = __ldg(batch + node);
        atomicAdd(&g_gbuf[g], acc);
        atomicAdd(&g_gbuf[64 + g], 1.0f);
    }
}

// ---------------------------------------------------------------------------
__global__ void k_finalize(const float* __restrict__ blin, float* __restrict__ out) {
    int g = threadIdx.x;
    if (g < 64) out[g] = g_gbuf[g] / fmaxf(g_gbuf[64 + g], 1.0f) + blin[0];
}

// ---------------------------------------------------------------------------
extern "C" void kernel_launch(void* const* d_in, const int* in_sizes, int n_in,
                              void* d_out, int out_size)
{
    const float* x     = (const float*)d_in[0];
    const int*   eidx  = (const int*)d_in[1];
    const int*   batch = (const int*)d_in[2];
    const float* W1    = (const float*)d_in[3];
    const float* b1    = (const float*)d_in[4];
    const float* W2    = (const float*)d_in[5];
    const float* b2    = (const float*)d_in[6];
    const float* Wlin  = (const float*)d_in[7];
    const float* blin  = (const float*)d_in[8];
    float* out = (float*)d_out;

    const int N = in_sizes[0] / 128;   // 50000
    const int E = in_sizes[1] / 2;     // 800000
    const int* src = eidx;
    const int* dst = eidx + E;

    const int T = 256;

    // degree + norm
    k_deg_init<<<(N + T - 1) / T, T>>>(N);
    k_deg_count<<<(E + T - 1) / T, T>>>(dst, E);
    k_dinv_zero<<<(N * 16 + T - 1) / T, T>>>(N);

    // layer 1
    k_gemm<128><<<(N + 63) / 64, 256>>>(x, W1, N);
    {
        long long w = (long long)E * 16;
        k_scatter<<<(int)((w + T - 1) / T), T>>>(src, dst, E);
    }
    k_post1<<<(N * 16 + T - 1) / T, T>>>(b1, N);

    // layer 2
    k_zero2<<<(N * 16 + T - 1) / T, T>>>(N);
    k_gemm<64><<<(N + 63) / 64, 256>>>(nullptr, W2, N);
    {
        long long w = (long long)E * 16;
        k_scatter<<<(int)((w + T - 1) / T), T>>>(src, dst, E);
    }

    // fused post + pooling head
    k_post2_reduce<<<(N * 32 + T - 1) / T, T>>>(b2, Wlin, batch, N);
    k_finalize<<<1, 64>>>(blin, out);
}

// round 5
// speedup vs baseline: 1.4212x; 1.4103x over previous
#include <cuda_runtime.h>
#include <cuda_bf16.h>

// GCN via CSR gather (no scatter atomics on features):
//   hs  = (X @ W) * dinv[row]
//   out_i = relu( dinv_i * ( sum_{e: dst=i} hs[src_e] + hs_i ) + b )
// CSR (edges binned by dst) built once per call, reused by both layers.

#define NN 50000
#define NE 800000
#define HID 64

// ---- scratch (device globals; referenced only from device code) ----
__device__ __align__(16) float g_hs[NN * HID];
__device__ __align__(16) float g_out1[NN * HID];
__device__ __align__(16) float g_dinv[NN];
__device__ int   g_ideg[NN];
__device__ int   g_pos[NN];
__device__ int   g_rowstart[NN];
__device__ int   g_cursor[NN];
__device__ int   g_esrc[NE];
__device__ int   g_bsum[64];
__device__ int   g_boff[64];
__device__ __align__(16) float g_gbuf[128];  // [0:64) sums, [64:128) counts

// ---------------------------------------------------------------------------
__global__ void k_zero(int n) {
    int i = blockIdx.x * blockDim.x + threadIdx.x;
    if (i < n) g_ideg[i] = 0;
    if (i < 128) g_gbuf[i] = 0.0f;
}

__global__ void k_count(const int* __restrict__ dst, int ne) {
    int e = blockIdx.x * blockDim.x + threadIdx.x;
    if (e < ne) atomicAdd(&g_ideg[dst[e]], 1);
}

// exclusive scan of g_ideg, 1024-chunks
__global__ __launch_bounds__(1024) void k_scan1(int n) {
    __shared__ int sh[1024];
    int i = blockIdx.x * 1024 + threadIdx.x;
    int v = (i < n) ? g_ideg[i] : 0;
    sh[threadIdx.x] = v;
    __syncthreads();
    for (int off = 1; off < 1024; off <<= 1) {
        int t = (threadIdx.x >= off) ? sh[threadIdx.x - off] : 0;
        __syncthreads();
        sh[threadIdx.x] += t;
        __syncthreads();
    }
    int incl = sh[threadIdx.x];
    if (i < n) g_pos[i] = incl - v;           // exclusive within block
    if (threadIdx.x == 1023) g_bsum[blockIdx.x] = incl;
}

__global__ void k_scan2(int nb) {
    if (threadIdx.x == 0) {
        int run = 0;
        for (int b = 0; b < nb; b++) { g_boff[b] = run; run += g_bsum[b]; }
    }
}

__global__ void k_scan3(int n) {
    int i = blockIdx.x * blockDim.x + threadIdx.x;
    if (i >= n) return;
    int base = g_pos[i] + g_boff[i >> 10];
    g_rowstart[i] = base;
    g_cursor[i]   = base;
    g_dinv[i]     = rsqrtf((float)g_ideg[i] + 1.0f);
}

__global__ void k_fill(const int* __restrict__ src, const int* __restrict__ dst, int ne) {
    int e = blockIdx.x * blockDim.x + threadIdx.x;
    if (e >= ne) return;
    int p = atomicAdd(&g_cursor[dst[e]], 1);
    g_esrc[p] = src[e];
}

// ---------------------------------------------------------------------------
// GEMM: g_hs[r,0:64] = (X[r,0:K] @ W[K,64]) * dinv[r]
// 128-row x 64-col block tile, 256 threads, 8x4 per-thread acc, K-chunk 32.
// Xin == nullptr -> read g_out1 (layer 2).
template <int K>
__global__ __launch_bounds__(256) void k_gemm(
    const float* __restrict__ Xin, const float* __restrict__ W, int nrows)
{
    const float* __restrict__ X = Xin ? Xin : g_out1;

    __shared__ float Xs[32][132];   // [k][row], pad 132 (=4 mod 32) conflict-free
    __shared__ float Ws[32][64];

    const int tid  = threadIdx.x;
    const int row0 = blockIdx.x * 128;
    const int tx   = tid & 15;      // cols tx*4 .. tx*4+3
    const int ty   = tid >> 4;      // rows ty*8 .. ty*8+7

    float acc[8][4] = {};

    for (int k0 = 0; k0 < K; k0 += 32) {
        // W chunk [32 x 64]
        for (int i = tid; i < 32 * 16; i += 256) {
            reinterpret_cast<float4*>(&Ws[0][0])[i] =
                reinterpret_cast<const float4*>(W + (size_t)k0 * 64)[i];
        }
        // X chunk [128 rows x 32 k], stored transposed Xs[k][row]
        for (int f = tid; f < 128 * 8; f += 256) {   // 8 float4 per row
            int r = f >> 3;
            int c = (f & 7) * 4;
            int gr = row0 + r;
            float4 v = make_float4(0.f, 0.f, 0.f, 0.f);
            if (gr < nrows)
                v = *reinterpret_cast<const float4*>(X + (size_t)gr * K + k0 + c);
            Xs[c + 0][r] = v.x; Xs[c + 1][r] = v.y;
            Xs[c + 2][r] = v.z; Xs[c + 3][r] = v.w;
        }
        __syncthreads();

        #pragma unroll 8
        for (int kk = 0; kk < 32; kk++) {
            float4 wv = *reinterpret_cast<const float4*>(&Ws[kk][tx * 4]);
            float xr[8];
            #pragma unroll
            for (int r = 0; r < 8; r++) xr[r] = Xs[kk][ty * 8 + r];
            #pragma unroll
            for (int r = 0; r < 8; r++) {
                acc[r][0] += xr[r] * wv.x;
                acc[r][1] += xr[r] * wv.y;
                acc[r][2] += xr[r] * wv.z;
                acc[r][3] += xr[r] * wv.w;
            }
        }
        __syncthreads();
    }

    #pragma unroll
    for (int r = 0; r < 8; r++) {
        int gr = row0 + ty * 8 + r;
        if (gr < nrows) {
            float s = g_dinv[gr];
            float4 o = make_float4(acc[r][0] * s, acc[r][1] * s,
                                   acc[r][2] * s, acc[r][3] * s);
            reinterpret_cast<float4*>(g_hs + (size_t)gr * 64)[tx] = o;
        }
    }
}

// ---------------------------------------------------------------------------
// Gather layer 1 + fused epilogue: out1 = relu(dinv*(sum_neigh + self) + b1)
// 16 threads per node, one float4 lane each.
__global__ __launch_bounds__(256) void k_gather1(const float* __restrict__ b1, int n)
{
    int gi = blockIdx.x * blockDim.x + threadIdx.x;
    int node = gi >> 4;
    if (node >= n) return;
    int q = gi & 15;

    const float4* __restrict__ H = reinterpret_cast<const float4*>(g_hs);
    int beg = g_rowstart[node];
    int end = beg + g_ideg[node];

    float4 acc = H[(size_t)node * 16 + q];   // self term
    int j = beg;
    for (; j + 4 <= end; j += 4) {
        int s0 = g_esrc[j], s1 = g_esrc[j + 1], s2 = g_esrc[j + 2], s3 = g_esrc[j + 3];
        float4 v0 = H[(size_t)s0 * 16 + q];
        float4 v1 = H[(size_t)s1 * 16 + q];
        float4 v2 = H[(size_t)s2 * 16 + q];
        float4 v3 = H[(size_t)s3 * 16 + q];
        acc.x += v0.x + v1.x + v2.x + v3.x;
        acc.y += v0.y + v1.y + v2.y + v3.y;
        acc.z += v0.z + v1.z + v2.z + v3.z;
        acc.w += v0.w + v1.w + v2.w + v3.w;
    }
    for (; j < end; j++) {
        int s = g_esrc[j];
        float4 v = H[(size_t)s * 16 + q];
        acc.x += v.x; acc.y += v.y; acc.z += v.z; acc.w += v.w;
    }

    float s = g_dinv[node];
    float4 bb = reinterpret_cast<const float4*>(b1)[q];
    float4 o;
    o.x = fmaxf(0.f, s * acc.x + bb.x);
    o.y = fmaxf(0.f, s * acc.y + bb.y);
    o.z = fmaxf(0.f, s * acc.z + bb.z);
    o.w = fmaxf(0.f, s * acc.w + bb.w);
    reinterpret_cast<float4*>(g_out1)[(size_t)node * 16 + q] = o;
}

// ---------------------------------------------------------------------------
// Gather layer 2 + fused head: v = relu(dinv*(sum+self)+b2); dot(v,Wlin) -> graph sum
__global__ __launch_bounds__(256) void k_gather2(
    const float* __restrict__ b2, const float* __restrict__ Wlin,
    const int* __restrict__ batch, int n)
{
    int gi = blockIdx.x * blockDim.x + threadIdx.x;
    int node = gi >> 4;
    if (node >= n) return;
    int q = gi & 15;

    const float4* __restrict__ H = reinterpret_cast<const float4*>(g_hs);
    int beg = g_rowstart[node];
    int end = beg + g_ideg[node];

    float4 acc = H[(size_t)node * 16 + q];
    int j = beg;
    for (; j + 4 <= end; j += 4) {
        int s0 = g_esrc[j], s1 = g_esrc[j + 1], s2 = g_esrc[j + 2], s3 = g_esrc[j + 3];
        float4 v0 = H[(size_t)s0 * 16 + q];
        float4 v1 = H[(size_t)s1 * 16 + q];
        float4 v2 = H[(size_t)s2 * 16 + q];
        float4 v3 = H[(size_t)s3 * 16 + q];
        acc.x += v0.x + v1.x + v2.x + v3.x;
        acc.y += v0.y + v1.y + v2.y + v3.y;
        acc.z += v0.z + v1.z + v2.z + v3.z;
        acc.w += v0.w + v1.w + v2.w + v3.w;
    }
    for (; j < end; j++) {
        int s = g_esrc[j];
        float4 v = H[(size_t)s * 16 + q];
        acc.x += v.x; acc.y += v.y; acc.z += v.z; acc.w += v.w;
    }

    float s = g_dinv[node];
    float4 bb = reinterpret_cast<const float4*>(b2)[q];
    float4 wl = reinterpret_cast<const float4*>(Wlin)[q];
    float dot =
        fmaxf(0.f, s * acc.x + bb.x) * wl.x +
        fmaxf(0.f, s * acc.y + bb.y) * wl.y +
        fmaxf(0.f, s * acc.z + bb.z) * wl.z +
        fmaxf(0.f, s * acc.w + bb.w) * wl.w;

    #pragma unroll
    for (int o = 8; o; o >>= 1) dot += __shfl_xor_sync(0xFFFFFFFFu, dot, o);
    if (q == 0) {
        int g = __ldg(batch + node);
        atomicAdd(&g_gbuf[g], dot);
        atomicAdd(&g_gbuf[64 + g], 1.0f);
    }
}

// ---------------------------------------------------------------------------
__global__ void k_finalize(const float* __restrict__ blin, float* __restrict__ out) {
    int g = threadIdx.x;
    if (g < 64) out[g] = g_gbuf[g] / fmaxf(g_gbuf[64 + g], 1.0f) + blin[0];
}

// ---------------------------------------------------------------------------
extern "C" void kernel_launch(void* const* d_in, const int* in_sizes, int n_in,
                              void* d_out, int out_size)
{
    const float* x     = (const float*)d_in[0];
    const int*   eidx  = (const int*)d_in[1];
    const int*   batch = (const int*)d_in[2];
    const float* W1    = (const float*)d_in[3];
    const float* b1    = (const float*)d_in[4];
    const float* W2    = (const float*)d_in[5];
    const float* b2    = (const float*)d_in[6];
    const float* Wlin  = (const float*)d_in[7];
    const float* blin  = (const float*)d_in[8];
    float* out = (float*)d_out;

    const int N = in_sizes[0] / 128;   // 50000
    const int E = in_sizes[1] / 2;     // 800000
    const int* src = eidx;
    const int* dst = eidx + E;

    const int T = 256;
    const int NB = (N + 1023) / 1024;

    // CSR build + dinv
    k_zero <<<(N + T - 1) / T, T>>>(N);
    k_count<<<(E + T - 1) / T, T>>>(dst, E);
    k_scan1<<<NB, 1024>>>(N);
    k_scan2<<<1, 32>>>(NB);
    k_scan3<<<(N + T - 1) / T, T>>>(N);
    k_fill <<<(E + T - 1) / T, T>>>(src, dst, E);

    // layer 1
    k_gemm<128><<<(N + 127) / 128, 256>>>(x, W1, N);
    k_gather1<<<(N * 16 + T - 1) / T, T>>>(b1, N);

    // layer 2
    k_gemm<64><<<(N + 127) / 128, 256>>>(nullptr, W2, N);
    k_gather2<<<(N * 16 + T - 1) / T, T>>>(b2, Wlin, batch, N);

    k_finalize<<<1, 64>>>(blin, out);
}

// round 6
// speedup vs baseline: 1.4912x; 1.0492x over previous
#include <cuda_runtime.h>
#include <cuda_fp16.h>
#include <cuda_bf16.h>

// GCN via CSR gather, fp16 feature storage, f32x2 packed-FMA GEMMs.
//   hs  = (X @ W) * dinv[row]            (fp32 compute, fp16 store)
//   out_i = relu( dinv_i * ( sum_{dst=i} hs[src] + hs_i ) + b )

#define NN 50000
#define NE 800000
#define HID 64

// ---- scratch (device globals; referenced only from device code) ----
__device__ __align__(16) uint2 g_hs[NN * 16];    // fp16 rows: 64 half = 16 uint2
__device__ __align__(16) uint2 g_out1[NN * 16];  // layer-1 activations, fp16
__device__ __align__(16) float g_dinv[NN];
__device__ int   g_ideg[NN];
__device__ int   g_pos[NN];
__device__ int   g_rowstart[NN];
__device__ int   g_cursor[NN];
__device__ int   g_esrc[NE];
__device__ int   g_bsum[64];
__device__ int   g_boff[64];
__device__ __align__(16) float g_gbuf[128];  // [0:64) sums, [64:128) counts

// ---------------------------------------------------------------------------
__global__ void k_zero(int n) {
    int i = blockIdx.x * blockDim.x + threadIdx.x;
    if (i < n) g_ideg[i] = 0;
    if (i < 128) g_gbuf[i] = 0.0f;
}

__global__ void k_count(const int* __restrict__ dst, int ne) {
    int e = blockIdx.x * blockDim.x + threadIdx.x;
    if (e < ne) atomicAdd(&g_ideg[dst[e]], 1);
}

// exclusive scan of g_ideg, 1024-chunks
__global__ __launch_bounds__(1024) void k_scan1(int n) {
    __shared__ int sh[1024];
    int i = blockIdx.x * 1024 + threadIdx.x;
    int v = (i < n) ? g_ideg[i] : 0;
    sh[threadIdx.x] = v;
    __syncthreads();
    for (int off = 1; off < 1024; off <<= 1) {
        int t = (threadIdx.x >= off) ? sh[threadIdx.x - off] : 0;
        __syncthreads();
        sh[threadIdx.x] += t;
        __syncthreads();
    }
    int incl = sh[threadIdx.x];
    if (i < n) g_pos[i] = incl - v;
    if (threadIdx.x == 1023) g_bsum[blockIdx.x] = incl;
}

// parallel scan of (<=64) block sums
__global__ void k_scan2(int nb) {
    int t = threadIdx.x;                       // 64 threads
    int v = (t < nb) ? g_bsum[t] : 0;
    int incl = v;
    #pragma unroll
    for (int o = 1; o < 32; o <<= 1) {
        int u = __shfl_up_sync(0xFFFFFFFFu, incl, o);
        if ((t & 31) >= o) incl += u;
    }
    __shared__ int ws[2];
    if ((t & 31) == 31) ws[t >> 5] = incl;
    __syncthreads();
    if (t >= 32) incl += ws[0];
    if (t < nb) g_boff[t] = incl - v;
}

__global__ void k_scan3(int n) {
    int i = blockIdx.x * blockDim.x + threadIdx.x;
    if (i >= n) return;
    int base = g_pos[i] + g_boff[i >> 10];
    g_rowstart[i] = base;
    g_cursor[i]   = base;
    g_dinv[i]     = rsqrtf((float)g_ideg[i] + 1.0f);
}

__global__ void k_fill(const int* __restrict__ src, const int* __restrict__ dst, int ne) {
    int e = blockIdx.x * blockDim.x + threadIdx.x;
    if (e >= ne) return;
    int p = atomicAdd(&g_cursor[dst[e]], 1);
    g_esrc[p] = src[e];
}

// ---------------------------------------------------------------------------
// GEMM: g_hs[r,0:64](fp16) = (X[r,0:K] @ W[K,64]) * dinv[r]
// HALF_IN: read X from g_out1 (fp16); else fp32 Xin.
// 128-row x 64-col tile, 256 threads, per-thread 4 row-pairs x 4 cols in
// packed f32x2 accumulators, inner loop uses fma.rn.f32x2.
template <int K, bool HALF_IN>
__global__ __launch_bounds__(256) void k_gemm(
    const float* __restrict__ Xin, const float* __restrict__ W, int nrows)
{
    __shared__ float Xs[32][132];   // [k][row], 8B-aligned rows (132*4=528B)
    __shared__ float Ws[32][64];

    const int tid  = threadIdx.x;
    const int row0 = blockIdx.x * 128;
    const int tx   = tid & 15;      // cols tx*4 .. tx*4+3
    const int ty   = tid >> 4;      // rows ty*8 .. ty*8+7

    unsigned long long acc2[4][4];  // [row-pair][col], packed {row2p, row2p+1}
    #pragma unroll
    for (int p = 0; p < 4; p++)
        #pragma unroll
        for (int c = 0; c < 4; c++) acc2[p][c] = 0ull;

    for (int k0 = 0; k0 < K; k0 += 32) {
        // W chunk [32 x 64]
        for (int i = tid; i < 32 * 16; i += 256) {
            reinterpret_cast<float4*>(&Ws[0][0])[i] =
                reinterpret_cast<const float4*>(W + (size_t)k0 * 64)[i];
        }
        // X chunk [128 rows x 32 k], transposed into Xs[k][row]
        if (!HALF_IN) {
            for (int f = tid; f < 128 * 8; f += 256) {  // 8 float4 per row
                int r = f >> 3;
                int c = (f & 7) * 4;
                int gr = row0 + r;
                float4 v = make_float4(0.f, 0.f, 0.f, 0.f);
                if (gr < nrows)
                    v = *reinterpret_cast<const float4*>(Xin + (size_t)gr * K + k0 + c);
                Xs[c + 0][r] = v.x; Xs[c + 1][r] = v.y;
                Xs[c + 2][r] = v.z; Xs[c + 3][r] = v.w;
            }
        } else {
            const uint4* X4 = reinterpret_cast<const uint4*>(g_out1);  // 8 uint4/row
            for (int f = tid; f < 128 * 4; f += 256) {  // 4 uint4 (8 halfs) per row
                int r  = f >> 2;
                int c8 = (f & 3) * 8;
                int gr = row0 + r;
                uint4 u = make_uint4(0u, 0u, 0u, 0u);
                if (gr < nrows)
                    u = X4[(size_t)gr * 8 + (k0 >> 3) + (f & 3)];
                float2 f0 = __half22float2(*reinterpret_cast<__half2*>(&u.x));
                float2 f1 = __half22float2(*reinterpret_cast<__half2*>(&u.y));
                float2 f2 = __half22float2(*reinterpret_cast<__half2*>(&u.z));
                float2 f3 = __half22float2(*reinterpret_cast<__half2*>(&u.w));
                Xs[c8 + 0][r] = f0.x; Xs[c8 + 1][r] = f0.y;
                Xs[c8 + 2][r] = f1.x; Xs[c8 + 3][r] = f1.y;
                Xs[c8 + 4][r] = f2.x; Xs[c8 + 5][r] = f2.y;
                Xs[c8 + 6][r] = f3.x; Xs[c8 + 7][r] = f3.y;
            }
        }
        __syncthreads();

        #pragma unroll 4
        for (int kk = 0; kk < 32; kk++) {
            float4 wv = *reinterpret_cast<const float4*>(&Ws[kk][tx * 4]);
            unsigned long long w2[4];
            asm("mov.b64 %0,{%1,%1};" : "=l"(w2[0]) : "f"(wv.x));
            asm("mov.b64 %0,{%1,%1};" : "=l"(w2[1]) : "f"(wv.y));
            asm("mov.b64 %0,{%1,%1};" : "=l"(w2[2]) : "f"(wv.z));
            asm("mov.b64 %0,{%1,%1};" : "=l"(w2[3]) : "f"(wv.w));
            #pragma unroll
            for (int p = 0; p < 4; p++) {
                unsigned long long xp =
                    *reinterpret_cast<const unsigned long long*>(&Xs[kk][ty * 8 + 2 * p]);
                #pragma unroll
                for (int c = 0; c < 4; c++) {
                    asm("fma.rn.f32x2 %0,%1,%2,%0;"
                        : "+l"(acc2[p][c]) : "l"(xp), "l"(w2[c]));
                }
            }
        }
        __syncthreads();
    }

    // epilogue: scale by dinv, convert to fp16, store rows
    #pragma unroll
    for (int p = 0; p < 4; p++) {
        float lo[4], hi[4];
        #pragma unroll
        for (int c = 0; c < 4; c++) {
            lo[c] = __uint_as_float((unsigned)(acc2[p][c] & 0xFFFFFFFFull));
            hi[c] = __uint_as_float((unsigned)(acc2[p][c] >> 32));
        }
        int r0 = row0 + ty * 8 + 2 * p;
        if (r0 < nrows) {
            float s = g_dinv[r0];
            __half2 h01 = __floats2half2_rn(lo[0] * s, lo[1] * s);
            __half2 h23 = __floats2half2_rn(lo[2] * s, lo[3] * s);
            uint2 u;
            u.x = *reinterpret_cast<unsigned*>(&h01);
            u.y = *reinterpret_cast<unsigned*>(&h23);
            g_hs[(size_t)r0 * 16 + tx] = u;
        }
        int r1 = r0 + 1;
        if (r1 < nrows) {
            float s = g_dinv[r1];
            __half2 h01 = __floats2half2_rn(hi[0] * s, hi[1] * s);
            __half2 h23 = __floats2half2_rn(hi[2] * s, hi[3] * s);
            uint2 u;
            u.x = *reinterpret_cast<unsigned*>(&h01);
            u.y = *reinterpret_cast<unsigned*>(&h23);
            g_hs[(size_t)r1 * 16 + tx] = u;
        }
    }
}

// ---------------------------------------------------------------------------
// Gather helpers: 16 lanes/node, lane q covers cols 4q..4q+3 (one uint2 = 4 half)
__device__ __forceinline__ void acc_row(float (&a)[4], uint2 u) {
    float2 f01 = __half22float2(*reinterpret_cast<__half2*>(&u.x));
    float2 f23 = __half22float2(*reinterpret_cast<__half2*>(&u.y));
    a[0] += f01.x; a[1] += f01.y; a[2] += f23.x; a[3] += f23.y;
}

// Gather layer 1 + epilogue: out1 = relu(dinv*(sum + self) + b1), fp16 store
__global__ __launch_bounds__(256) void k_gather1(const float* __restrict__ b1, int n)
{
    int gi = blockIdx.x * blockDim.x + threadIdx.x;
    int node = gi >> 4;
    if (node >= n) return;
    int q = gi & 15;

    int beg = g_rowstart[node];
    int end = beg + g_ideg[node];

    float a[4] = {0.f, 0.f, 0.f, 0.f};
    acc_row(a, g_hs[(size_t)node * 16 + q]);   // self
    int j = beg;
    for (; j + 4 <= end; j += 4) {
        int s0 = g_esrc[j], s1 = g_esrc[j + 1], s2 = g_esrc[j + 2], s3 = g_esrc[j + 3];
        uint2 u0 = g_hs[(size_t)s0 * 16 + q];
        uint2 u1 = g_hs[(size_t)s1 * 16 + q];
        uint2 u2 = g_hs[(size_t)s2 * 16 + q];
        uint2 u3 = g_hs[(size_t)s3 * 16 + q];
        acc_row(a, u0); acc_row(a, u1); acc_row(a, u2); acc_row(a, u3);
    }
    for (; j < end; j++) acc_row(a, g_hs[(size_t)g_esrc[j] * 16 + q]);

    float s = g_dinv[node];
    float4 bb = reinterpret_cast<const float4*>(b1)[q];
    float o0 = fmaxf(0.f, s * a[0] + bb.x);
    float o1 = fmaxf(0.f, s * a[1] + bb.y);
    float o2 = fmaxf(0.f, s * a[2] + bb.z);
    float o3 = fmaxf(0.f, s * a[3] + bb.w);
    __half2 h01 = __floats2half2_rn(o0, o1);
    __half2 h23 = __floats2half2_rn(o2, o3);
    uint2 u;
    u.x = *reinterpret_cast<unsigned*>(&h01);
    u.y = *reinterpret_cast<unsigned*>(&h23);
    g_out1[(size_t)node * 16 + q] = u;
}

// Gather layer 2 + fused head: v = relu(dinv*(sum+self)+b2); dot(v,Wlin)
__global__ __launch_bounds__(256) void k_gather2(
    const float* __restrict__ b2, const float* __restrict__ Wlin,
    const int* __restrict__ batch, int n)
{
    int gi = blockIdx.x * blockDim.x + threadIdx.x;
    int node = gi >> 4;
    if (node >= n) return;
    int q = gi & 15;

    int beg = g_rowstart[node];
    int end = beg + g_ideg[node];

    float a[4] = {0.f, 0.f, 0.f, 0.f};
    acc_row(a, g_hs[(size_t)node * 16 + q]);   // self
    int j = beg;
    for (; j + 4 <= end; j += 4) {
        int s0 = g_esrc[j], s1 = g_esrc[j + 1], s2 = g_esrc[j + 2], s3 = g_esrc[j + 3];
        uint2 u0 = g_hs[(size_t)s0 * 16 + q];
        uint2 u1 = g_hs[(size_t)s1 * 16 + q];
        uint2 u2 = g_hs[(size_t)s2 * 16 + q];
        uint2 u3 = g_hs[(size_t)s3 * 16 + q];
        acc_row(a, u0); acc_row(a, u1); acc_row(a, u2); acc_row(a, u3);
    }
    for (; j < end; j++) acc_row(a, g_hs[(size_t)g_esrc[j] * 16 + q]);

    float s = g_dinv[node];
    float4 bb = reinterpret_cast<const float4*>(b2)[q];
    float4 wl = reinterpret_cast<const float4*>(Wlin)[q];
    float dot =
        fmaxf(0.f, s * a[0] + bb.x) * wl.x +
        fmaxf(0.f, s * a[1] + bb.y) * wl.y +
        fmaxf(0.f, s * a[2] + bb.z) * wl.z +
        fmaxf(0.f, s * a[3] + bb.w) * wl.w;

    #pragma unroll
    for (int o = 8; o; o >>= 1) dot += __shfl_xor_sync(0xFFFFFFFFu, dot, o);
    if (q == 0) {
        int g = __ldg(batch + node);
        atomicAdd(&g_gbuf[g], dot);
        atomicAdd(&g_gbuf[64 + g], 1.0f);
    }
}

// ---------------------------------------------------------------------------
__global__ void k_finalize(const float* __restrict__ blin, float* __restrict__ out) {
    int g = threadIdx.x;
    if (g < 64) out[g] = g_gbuf[g] / fmaxf(g_gbuf[64 + g], 1.0f) + blin[0];
}

// ---------------------------------------------------------------------------
extern "C" void kernel_launch(void* const* d_in, const int* in_sizes, int n_in,
                              void* d_out, int out_size)
{
    const float* x     = (const float*)d_in[0];
    const int*   eidx  = (const int*)d_in[1];
    const int*   batch = (const int*)d_in[2];
    const float* W1    = (const float*)d_in[3];
    const float* b1    = (const float*)d_in[4];
    const float* W2    = (const float*)d_in[5];
    const float* b2    = (const float*)d_in[6];
    const float* Wlin  = (const float*)d_in[7];
    const float* blin  = (const float*)d_in[8];
    float* out = (float*)d_out;

    const int N = in_sizes[0] / 128;   // 50000
    const int E = in_sizes[1] / 2;     // 800000
    const int* src = eidx;
    const int* dst = eidx + E;

    const int T = 256;
    const int NB = (N + 1023) / 1024;

    // CSR build + dinv
    k_zero <<<(N + T - 1) / T, T>>>(N);
    k_count<<<(E + T - 1) / T, T>>>(dst, E);
    k_scan1<<<NB, 1024>>>(N);
    k_scan2<<<1, 64>>>(NB);
    k_scan3<<<(N + T - 1) / T, T>>>(N);
    k_fill <<<(E + T - 1) / T, T>>>(src, dst, E);

    // layer 1
    k_gemm<128, false><<<(N + 127) / 128, 256>>>(x, W1, N);
    k_gather1<<<(N * 16 + T - 1) / T, T>>>(b1, N);

    // layer 2
    k_gemm<64, true><<<(N + 127) / 128, 256>>>(nullptr, W2, N);
    k_gather2<<<(N * 16 + T - 1) / T, T>>>(b2, Wlin, batch, N);

    k_finalize<<<1, 64>>>(blin, out);
}